// round 9
// baseline (speedup 1.0000x reference)
#include <cuda_runtime.h>
#include <cuda_bf16.h>

#define NN 100000
#define HH 128
#define NE 1600000
#define NB 98            // ceil(NN / 1024) scan chunks
#define GB 888           // persistent build grid: 6 blocks/SM x 148 SMs

// Scratch (allocation-free rule: __device__ globals, zero-initialized)
__device__ __align__(16) float g_S[(size_t)NN * HH];
__device__ __align__(16) float g_I[(size_t)NN * HH];
__device__ int g_cnt[NN];          // histogram (zeroed via memset node)
__device__ int g_scan[NN];         // chunk-local exclusive prefix
__device__ int g_cur[NN];          // fill cursor (same init as g_scan)
__device__ int g_bsum[128];        // per-chunk totals -> exclusive-scanned
__device__ int g_csr[NE];
__device__ unsigned g_bar_count;   // grid barrier state (self-resetting)
__device__ volatile unsigned g_bar_gen;

// ---------------------------------------------------------------------------
// packed f32x2 helpers
// ---------------------------------------------------------------------------
__device__ __forceinline__ void fma2(unsigned long long& a,
                                     unsigned long long x,
                                     unsigned long long w) {
    asm("fma.rn.f32x2 %0, %1, %2, %0;" : "+l"(a) : "l"(x), "l"(w));
}
__device__ __forceinline__ float unpack_sum(unsigned long long a) {
    float lo, hi;
    asm("mov.b64 {%0, %1}, %2;" : "=f"(lo), "=f"(hi) : "l"(a));
    return lo + hi;
}

// ---------------------------------------------------------------------------
// software grid barrier (gen-relative, so no reset needed across launches)
// ---------------------------------------------------------------------------
__device__ __forceinline__ void grid_barrier() {
    __syncthreads();
    if (threadIdx.x == 0) {
        __threadfence();
        unsigned gen = g_bar_gen;
        unsigned t = atomicAdd(&g_bar_count, 1u);
        if (t == GB - 1) {
            atomicExch(&g_bar_count, 0u);
            __threadfence();
            g_bar_gen = gen + 1;
        } else {
            while (g_bar_gen == gen) __nanosleep(64);
            __threadfence();
        }
    }
    __syncthreads();
}

// ---------------------------------------------------------------------------
// K1 (persistent): hist -> chunk scan -> bsum scan -> CSR fill, one kernel.
// g_cnt must be zeroed beforehand (memset node). int64 detection inline.
// ---------------------------------------------------------------------------
__global__ void __launch_bounds__(256, 6) build_kernel(
    const void* __restrict__ rowsp, const void* __restrict__ colsp) {
    __shared__ int s_is64;
    __shared__ int s_w[8];

    if (threadIdx.x == 0) {
        const unsigned* ru = (const unsigned*)rowsp;
        const unsigned* cu = (const unsigned*)colsp;
        unsigned v = 0;
#pragma unroll
        for (int k = 1; k < 16; k += 2) v |= ru[k] | cu[k];
        s_is64 = (v == 0u) ? 1 : 0;
    }
    __syncthreads();
    const int is64 = s_is64;
    const long long* __restrict__ rows64 = (const long long*)rowsp;
    const int*       __restrict__ rows32 = (const int*)rowsp;
    const long long* __restrict__ cols64 = (const long long*)colsp;
    const int*       __restrict__ cols32 = (const int*)colsp;

    const int gt = blockIdx.x * 256 + threadIdx.x;
    const int stride = GB * 256;

    // phase 1: histogram
    for (int i = gt; i < NE; i += stride) {
        int r = is64 ? (int)rows64[i] : rows32[i];
        atomicAdd(&g_cnt[r], 1);
    }
    grid_barrier();

    // phase 2: per-chunk (1024-wide) exclusive scan, blocks 0..NB-1
    if (blockIdx.x < NB) {
        const int lane = threadIdx.x & 31, wid = threadIdx.x >> 5;
        int base = blockIdx.x * 1024 + threadIdx.x * 4;
        int v0 = (base + 0 < NN) ? g_cnt[base + 0] : 0;
        int v1 = (base + 1 < NN) ? g_cnt[base + 1] : 0;
        int v2 = (base + 2 < NN) ? g_cnt[base + 2] : 0;
        int v3 = (base + 3 < NN) ? g_cnt[base + 3] : 0;
        int t = v0 + v1 + v2 + v3;
        int xt = t;
#pragma unroll
        for (int d = 1; d < 32; d <<= 1) {
            int u = __shfl_up_sync(0xFFFFFFFFu, xt, d);
            if (lane >= d) xt += u;
        }
        if (lane == 31) s_w[wid] = xt;
        __syncthreads();
        if (threadIdx.x < 8) {
            int a = s_w[threadIdx.x];
#pragma unroll
            for (int d = 1; d < 8; d <<= 1) {
                int u = __shfl_up_sync(0xFFu, a, d);
                if ((int)threadIdx.x >= d) a += u;
            }
            s_w[threadIdx.x] = a;   // inclusive warp-sum prefix
        }
        __syncthreads();
        int woff = (wid == 0) ? 0 : s_w[wid - 1];
        int ex = woff + (xt - t);           // thread-exclusive offset
        int e0 = ex, e1 = ex + v0, e2 = e1 + v1, e3 = e2 + v2;
        if (base + 0 < NN) { g_scan[base + 0] = e0; g_cur[base + 0] = e0; }
        if (base + 1 < NN) { g_scan[base + 1] = e1; g_cur[base + 1] = e1; }
        if (base + 2 < NN) { g_scan[base + 2] = e2; g_cur[base + 2] = e2; }
        if (base + 3 < NN) { g_scan[base + 3] = e3; g_cur[base + 3] = e3; }
        if (threadIdx.x == 255) g_bsum[blockIdx.x] = ex + t;  // chunk total
    }
    grid_barrier();

    // phase 3: block 0 warp 0 exclusive-scans the NB chunk totals in place
    if (blockIdx.x == 0 && threadIdx.x < 32) {
        int lane = threadIdx.x, carry = 0;
        for (int base = 0; base < NB; base += 32) {
            int bv = (base + lane < NB) ? g_bsum[base + lane] : 0;
            int bx = bv;
#pragma unroll
            for (int d = 1; d < 32; d <<= 1) {
                int u = __shfl_up_sync(0xFFFFFFFFu, bx, d);
                if (lane >= d) bx += u;
            }
            if (base + lane < NB) g_bsum[base + lane] = carry + bx - bv;
            carry += __shfl_sync(0xFFFFFFFFu, bx, 31);
        }
    }
    grid_barrier();

    // phase 4: fill CSR columns
    for (int i = gt; i < NE; i += stride) {
        int r, c;
        if (is64) { r = (int)rows64[i]; c = (int)cols64[i]; }
        else      { r = rows32[i];      c = cols32[i]; }
        int pos = g_bsum[r >> 10] + atomicAdd(&g_cur[r], 1);
        g_csr[pos] = c;
    }
}

// ---------------------------------------------------------------------------
// K2/K3: plane GEMM. s=0: S plane -> g_S. s=1: I plane -> g_I, plus fused
// out[2] = gamma*I and out[3] = 0. Packed f32x2 FMAs, 4 nodes x 8 outs/thread.
// ---------------------------------------------------------------------------
__global__ __launch_bounds__(256) void gemm_sig_kernel(
    const float* __restrict__ x, const float* __restrict__ W,
    const float* __restrict__ b, float* __restrict__ out, int s) {
    const int tid = threadIdx.x;
    const int ng  = tid & 15;
    const int og  = tid >> 4;
    const int n0  = blockIdx.x * 64 + ng * 4;
    const int o0  = og * 8;

    unsigned long long acc[4][8];
#pragma unroll
    for (int i = 0; i < 4; i++)
#pragma unroll
        for (int j = 0; j < 8; j++) acc[i][j] = 0ULL;

    int nidx[4];
#pragma unroll
    for (int i = 0; i < 4; i++) {
        int n = n0 + i;
        nidx[i] = (n < NN) ? n : (NN - 1);
    }

    const ulonglong2* __restrict__ xp =
        (const ulonglong2*)(x + (size_t)s * NN * HH);
    const ulonglong2* __restrict__ wp = (const ulonglong2*)W;

#pragma unroll 2
    for (int h4 = 0; h4 < HH / 4; h4++) {
        ulonglong2 xv[4];
#pragma unroll
        for (int i = 0; i < 4; i++) xv[i] = xp[nidx[i] * (HH / 4) + h4];
        ulonglong2 wv[8];
#pragma unroll
        for (int j = 0; j < 8; j++) wv[j] = wp[(o0 + j) * (HH / 4) + h4];
#pragma unroll
        for (int j = 0; j < 8; j++)
#pragma unroll
            for (int i = 0; i < 4; i++) {
                fma2(acc[i][j], xv[i].x, wv[j].x);
                fma2(acc[i][j], xv[i].y, wv[j].y);
            }
    }

    float* dst = (s == 0) ? g_S : g_I;
#pragma unroll
    for (int i = 0; i < 4; i++) {
        int n = n0 + i;
        if (n >= NN) continue;
        float v[8];
#pragma unroll
        for (int j = 0; j < 8; j++) {
            float z = unpack_sum(acc[i][j]) + b[o0 + j];
            v[j] = 1.0f / (1.0f + __expf(-z));
        }
        size_t base = (size_t)n * HH + o0;
        *(float4*)(dst + base)     = make_float4(v[0], v[1], v[2], v[3]);
        *(float4*)(dst + base + 4) = make_float4(v[4], v[5], v[6], v[7]);

        if (s == 1) {
            float gamma = x[((size_t)3 * NN + n) * HH + 1];
            float4 z4 = make_float4(0.f, 0.f, 0.f, 0.f);
            *(float4*)(out + (size_t)2 * NN * HH + base) =
                make_float4(gamma * v[0], gamma * v[1], gamma * v[2], gamma * v[3]);
            *(float4*)(out + (size_t)2 * NN * HH + base + 4) =
                make_float4(gamma * v[4], gamma * v[5], gamma * v[6], gamma * v[7]);
            *(float4*)(out + (size_t)3 * NN * HH + base)     = z4;
            *(float4*)(out + (size_t)3 * NN * HH + base + 4) = z4;
        }
    }
}

// ---------------------------------------------------------------------------
// K4: gather + finalize. One warp per row; MLP=4 unroll. Reads gamma*I from
// out[2] (written by gemmI), writes only out[0]/out[1].
// ---------------------------------------------------------------------------
__global__ __launch_bounds__(256) void gather_kernel(
    const float* __restrict__ x, float* __restrict__ out) {
    int warp = (blockIdx.x * blockDim.x + threadIdx.x) >> 5;
    int lane = threadIdx.x & 31;
    if (warp >= NN) return;
    const int r = warp;
    int e   = g_scan[r] + g_bsum[r >> 10];
    int end = (r + 1 < NN) ? (g_scan[r + 1] + g_bsum[(r + 1) >> 10]) : NE;

    const float4* __restrict__ I4 = (const float4*)g_I;
    float4 sum = make_float4(0.f, 0.f, 0.f, 0.f);

    for (; e + 4 <= end; e += 4) {
        int c0 = g_csr[e];
        int c1 = g_csr[e + 1];
        int c2 = g_csr[e + 2];
        int c3 = g_csr[e + 3];
        float4 v0 = __ldg(&I4[(size_t)c0 * 32 + lane]);
        float4 v1 = __ldg(&I4[(size_t)c1 * 32 + lane]);
        float4 v2 = __ldg(&I4[(size_t)c2 * 32 + lane]);
        float4 v3 = __ldg(&I4[(size_t)c3 * 32 + lane]);
        sum.x += (v0.x + v1.x) + (v2.x + v3.x);
        sum.y += (v0.y + v1.y) + (v2.y + v3.y);
        sum.z += (v0.z + v1.z) + (v2.z + v3.z);
        sum.w += (v0.w + v1.w) + (v2.w + v3.w);
    }
    for (; e < end; e++) {
        int c = g_csr[e];
        float4 v = __ldg(&I4[(size_t)c * 32 + lane]);
        sum.x += v.x; sum.y += v.y; sum.z += v.z; sum.w += v.w;
    }

    float beta = x[((size_t)3 * NN + r) * HH];
    size_t idx = (size_t)r * 32 + lane;
    size_t plane = (size_t)NN * 32;
    float4 sv = ((const float4*)g_S)[idx];
    float4 gi = ((const float4*)out)[2 * plane + idx];

    float4 ds, di;
    ds.x = -beta * sum.x * sv.x;  di.x = -ds.x - gi.x;
    ds.y = -beta * sum.y * sv.y;  di.y = -ds.y - gi.y;
    ds.z = -beta * sum.z * sv.z;  di.z = -ds.z - gi.z;
    ds.w = -beta * sum.w * sv.w;  di.w = -ds.w - gi.w;

    float4* o4 = (float4*)out;
    o4[idx]         = ds;
    o4[plane + idx] = di;
}

// ---------------------------------------------------------------------------
// Streams/events created before main() (pre-baseline). Fallback: sequential.
// ---------------------------------------------------------------------------
namespace {
struct Ctx {
    cudaStream_t sA = nullptr, sB = nullptr;
    cudaEvent_t  eF = nullptr, eA = nullptr, eB = nullptr;
    void* cnt_addr = nullptr;
    bool ok = false;
    Ctx() {
        ok = (cudaStreamCreateWithFlags(&sA, cudaStreamNonBlocking) == cudaSuccess) &&
             (cudaStreamCreateWithFlags(&sB, cudaStreamNonBlocking) == cudaSuccess) &&
             (cudaEventCreateWithFlags(&eF, cudaEventDisableTiming) == cudaSuccess) &&
             (cudaEventCreateWithFlags(&eA, cudaEventDisableTiming) == cudaSuccess) &&
             (cudaEventCreateWithFlags(&eB, cudaEventDisableTiming) == cudaSuccess) &&
             (cudaGetSymbolAddress(&cnt_addr, g_cnt) == cudaSuccess);
    }
};
Ctx g_ctx;
}

extern "C" void kernel_launch(void* const* d_in, const int* in_sizes, int n_in,
                              void* d_out, int out_size) {
    const float* x = (const float*)d_in[0];
    const float* W = (const float*)d_in[1];
    const float* b = (const float*)d_in[2];
    const void* rows = d_in[3];
    const void* cols = d_in[4];
    float* out = (float*)d_out;

    const int gGemm = (NN + 63) / 64;

    if (g_ctx.ok) {
        cudaEventRecord(g_ctx.eF, 0);
        cudaStreamWaitEvent(g_ctx.sA, g_ctx.eF, 0);
        cudaStreamWaitEvent(g_ctx.sB, g_ctx.eF, 0);

        // CSR build chain on sA (launched FIRST so its 888 blocks land first)
        cudaMemsetAsync(g_ctx.cnt_addr, 0, NN * sizeof(int), g_ctx.sA);
        build_kernel<<<GB, 256, 0, g_ctx.sA>>>(rows, cols);

        // GEMM planes on sB (fills remaining occupancy, overlaps build)
        gemm_sig_kernel<<<gGemm, 256, 0, g_ctx.sB>>>(x, W, b, out, 1); // I plane
        gemm_sig_kernel<<<gGemm, 256, 0, g_ctx.sB>>>(x, W, b, out, 0); // S plane

        cudaEventRecord(g_ctx.eA, g_ctx.sA);
        cudaEventRecord(g_ctx.eB, g_ctx.sB);
        cudaStreamWaitEvent(0, g_ctx.eA, 0);
        cudaStreamWaitEvent(0, g_ctx.eB, 0);
    } else {
        cudaMemsetAsync(g_ctx.cnt_addr ? g_ctx.cnt_addr : (void*)0, 0,
                        NN * sizeof(int), 0);
        build_kernel<<<GB, 256>>>(rows, cols);
        gemm_sig_kernel<<<gGemm, 256>>>(x, W, b, out, 1);
        gemm_sig_kernel<<<gGemm, 256>>>(x, W, b, out, 0);
    }

    gather_kernel<<<(NN * 32 + 255) / 256, 256>>>(x, out);
}